// round 14
// baseline (speedup 1.0000x reference)
#include <cuda_runtime.h>
#include <cuda_fp16.h>

#define N_NODES 50000
#define N_EDGES 625000
#define D_FEAT  128
#define K_HOPS  10
#define SZ      (N_NODES * D_FEAT)

#define SCAN_TILE 512
#define N_TILES   ((N_NODES + SCAN_TILE - 1) / SCAN_TILE)   // 98

#define PROP_BLOCKS 296
#define PROP_THREADS 512
#define N_HW (PROP_BLOCKS * (PROP_THREADS / 16))   // 9472 half-warps

// ---------------------------------------------------------------------------
// Scratch (device globals — no allocation allowed anywhere)
// ---------------------------------------------------------------------------
__device__ __half g_hh[(size_t)K_HOPS * SZ];  // h_k (scaled) at slot k-1, 128 MB
__device__ __half g_xh[SZ];                   // fp16(x), 12.8 MB
__device__ int    g_deg[N_NODES];
__device__ int    g_rowptr[N_NODES + 1];
__device__ int    g_cursor[N_NODES];
__device__ int    g_col[N_EDGES];
__device__ float  g_w[K_HOPS + 1];
__device__ int    g_is64;
__device__ int    g_tilesum[N_TILES];
__device__ int    g_tileoff[N_TILES];
__device__ float  g_S0;              // max|x|
__device__ int    g_d[K_HOPS + 1];   // per-hop scale exponent d_k (precomputed)
__device__ int    g_maxdeg;

__device__ __forceinline__ void atomicMaxF(float* addr, float v) {
    atomicMax((int*)addr, __float_as_int(v));   // valid: non-negative floats
}

// ---------------------------------------------------------------------------
// 0) dtype detect + softmax(att) + zero per-launch scalars
// ---------------------------------------------------------------------------
__global__ void prep_kernel(const void* ei, const float* __restrict__ att) {
    if (threadIdx.x == 0 && blockIdx.x == 0) {
        const long long* p = (const long long*)ei;
        int is64 = 1;
        for (int i = 0; i < 64; i++) {
            long long v = p[i];
            if (v < 0 || v >= (long long)N_NODES) { is64 = 0; break; }
        }
        g_is64 = is64;

        float m = -1e30f;
        for (int i = 0; i <= K_HOPS; i++) m = fmaxf(m, att[i]);
        float e[K_HOPS + 1];
        float s = 0.f;
        for (int i = 0; i <= K_HOPS; i++) { e[i] = __expf(att[i] - m); s += e[i]; }
        float inv = 1.f / s;
        for (int i = 0; i <= K_HOPS; i++) g_w[i] = e[i] * inv;

        for (int i = 0; i <= K_HOPS; i++) g_d[i] = 0;
        g_S0 = 0.f;
        g_maxdeg = 0;
    }
}

// fused: x -> fp16 g_xh, max|x| -> g_S0, AND zero g_deg
__global__ void __launch_bounds__(256)
quantize_x_kernel(const float* __restrict__ x) {
    const int stride = gridDim.x * blockDim.x;
    int t = blockIdx.x * blockDim.x + threadIdx.x;

    for (int i = t; i < N_NODES; i += stride) g_deg[i] = 0;

    float m = 0.f;
    for (int i = t; i < SZ / 4; i += stride) {
        float4 v = __ldg(&((const float4*)x)[i]);
        m = fmaxf(m, fmaxf(fmaxf(fabsf(v.x), fabsf(v.y)),
                           fmaxf(fabsf(v.z), fabsf(v.w))));
        __half2 h01 = __floats2half2_rn(v.x, v.y);
        __half2 h23 = __floats2half2_rn(v.z, v.w);
        uint2 st;
        st.x = *(unsigned*)&h01;
        st.y = *(unsigned*)&h23;
        ((uint2*)g_xh)[i] = st;
    }
    for (int off = 16; off > 0; off >>= 1)
        m = fmaxf(m, __shfl_down_sync(0xFFFFFFFFu, m, off));
    if ((threadIdx.x & 31) == 0) atomicMaxF(&g_S0, m);
}

// ---------------------------------------------------------------------------
// CSR build
// ---------------------------------------------------------------------------
__global__ void hist_kernel(const void* __restrict__ ei) {
    int t = blockIdx.x * blockDim.x + threadIdx.x;
    int e = t * 4;
    if (e >= N_EDGES) return;
    int d0, d1, d2, d3;
    if (g_is64) {
        const longlong2* p = (const longlong2*)((const long long*)ei + N_EDGES);
        longlong2 a = p[t * 2];
        longlong2 b = p[t * 2 + 1];
        d0 = (int)a.x; d1 = (int)a.y; d2 = (int)b.x; d3 = (int)b.y;
    } else {
        int4 a = ((const int4*)((const int*)ei + N_EDGES))[t];
        d0 = a.x; d1 = a.y; d2 = a.z; d3 = a.w;
    }
    atomicAdd(&g_deg[d0], 1);
    if (e + 1 < N_EDGES) atomicAdd(&g_deg[d1], 1);
    if (e + 2 < N_EDGES) atomicAdd(&g_deg[d2], 1);
    if (e + 3 < N_EDGES) atomicAdd(&g_deg[d3], 1);
}

__global__ void __launch_bounds__(SCAN_TILE)
scan_reduce_kernel() {
    __shared__ int wsum[SCAN_TILE / 32];
    int i = blockIdx.x * SCAN_TILE + threadIdx.x;
    int v = (i < N_NODES) ? g_deg[i] : 0;
    int mx = v;
    for (int off = 16; off > 0; off >>= 1) {
        v  += __shfl_down_sync(0xFFFFFFFFu, v,  off);
        mx  = max(mx, __shfl_down_sync(0xFFFFFFFFu, mx, off));
    }
    int wid = threadIdx.x >> 5;
    if ((threadIdx.x & 31) == 0) { wsum[wid] = v; atomicMax(&g_maxdeg, mx); }
    __syncthreads();
    if (wid == 0) {
        int lane = threadIdx.x & 31;
        int s = (lane < SCAN_TILE / 32) ? wsum[lane] : 0;
        for (int off = 16; off > 0; off >>= 1)
            s += __shfl_down_sync(0xFFFFFFFFu, s, off);
        if (lane == 0) g_tilesum[blockIdx.x] = s;
    }
}

// tile-sum exclusive scan + fused deterministic scale plan
__global__ void scan_tiles_kernel() {
    __shared__ int wtot[4];
    int tid  = threadIdx.x;
    int lane = tid & 31;
    int wid  = tid >> 5;
    int v = (tid < N_TILES) ? g_tilesum[tid] : 0;
    int incl = v;
    for (int off = 1; off < 32; off <<= 1) {
        int u = __shfl_up_sync(0xFFFFFFFFu, incl, off);
        if (lane >= off) incl += u;
    }
    if (lane == 31) wtot[wid] = incl;
    __syncthreads();
    int base = 0;
    for (int w = 0; w < wid; w++) base += wtot[w];
    int excl = base + incl - v;
    if (tid < N_TILES) g_tileoff[tid] = excl;
    if (tid == N_TILES - 1) g_rowptr[N_NODES] = excl + v;

    // scale plan: bound chain S_k <= S_{k-1}*maxdeg*2^{-d_k} (exact pow2,
    // fp16 precision is scale-invariant; guarantees no overflow).
    if (tid == 0) {
        float S  = g_S0;
        float md = (float)g_maxdeg;
        for (int k = 1; k <= K_HOPS; k++) {
            float bound = S * md;
            int d = 0;
            if (bound > 32768.f) d = (int)ceilf(log2f(bound * (1.f / 32768.f)));
            g_d[k] = d;
            S = bound * exp2f(-(float)d);
        }
    }
}

__global__ void __launch_bounds__(SCAN_TILE)
scan_final_kernel() {
    __shared__ int wtot[SCAN_TILE / 32];
    int i    = blockIdx.x * SCAN_TILE + threadIdx.x;
    int lane = threadIdx.x & 31;
    int wid  = threadIdx.x >> 5;

    int v = (i < N_NODES) ? g_deg[i] : 0;
    int incl = v;
    for (int off = 1; off < 32; off <<= 1) {
        int u = __shfl_up_sync(0xFFFFFFFFu, incl, off);
        if (lane >= off) incl += u;
    }
    if (lane == 31) wtot[wid] = incl;
    __syncthreads();
    if (wid == 0) {
        int s = (lane < SCAN_TILE / 32) ? wtot[lane] : 0;
        int si = s;
        for (int off = 1; off < 32; off <<= 1) {
            int u = __shfl_up_sync(0xFFFFFFFFu, si, off);
            if (lane >= off) si += u;
        }
        if (lane < SCAN_TILE / 32) wtot[lane] = si - s;
    }
    __syncthreads();

    if (i < N_NODES) {
        int excl = g_tileoff[blockIdx.x] + wtot[wid] + incl - v;
        g_rowptr[i] = excl;
        g_cursor[i] = excl;
    }
}

__global__ void scatter_kernel(const void* __restrict__ ei) {
    int t = blockIdx.x * blockDim.x + threadIdx.x;
    int e = t * 4;
    if (e >= N_EDGES) return;
    int s0, s1, s2, s3, d0, d1, d2, d3;
    if (g_is64) {
        const long long* p = (const long long*)ei;
        longlong2 sa = ((const longlong2*)p)[t * 2];
        longlong2 sb = ((const longlong2*)p)[t * 2 + 1];
        longlong2 da = ((const longlong2*)(p + N_EDGES))[t * 2];
        longlong2 db = ((const longlong2*)(p + N_EDGES))[t * 2 + 1];
        s0 = (int)sa.x; s1 = (int)sa.y; s2 = (int)sb.x; s3 = (int)sb.y;
        d0 = (int)da.x; d1 = (int)da.y; d2 = (int)db.x; d3 = (int)db.y;
    } else {
        const int* p = (const int*)ei;
        int4 sa = ((const int4*)p)[t];
        int4 da = ((const int4*)(p + N_EDGES))[t];
        s0 = sa.x; s1 = sa.y; s2 = sa.z; s3 = sa.w;
        d0 = da.x; d1 = da.y; d2 = da.z; d3 = da.w;
    }
    { int q = atomicAdd(&g_cursor[d0], 1); g_col[q] = s0; }
    if (e + 1 < N_EDGES) { int q = atomicAdd(&g_cursor[d1], 1); g_col[q] = s1; }
    if (e + 2 < N_EDGES) { int q = atomicAdd(&g_cursor[d2], 1); g_col[q] = s2; }
    if (e + 3 < N_EDGES) { int q = atomicAdd(&g_cursor[d3], 1); g_col[q] = s3; }
}

// ---------------------------------------------------------------------------
// propagation hop k: half-warp per node with GRID-STRIDE node loop.
// 296 blocks x 512 threads = 9472 half-warps, each handling ~5.3 nodes:
// per-thread work concentrates toward the mean degree, flattening the
// ragged tail that each of the 10 dependent launches otherwise pays.
// No residency assumptions, no barriers — safe at any occupancy.
//   stored_k = (A * stored_{k-1}) * 2^{-d_k}   (exact pow2 scale)
// ---------------------------------------------------------------------------
__global__ void __launch_bounds__(PROP_THREADS)
prop_kernel(int k) {
    const int hw0 = (blockIdx.x * PROP_THREADS + threadIdx.x) >> 4;
    const int sub = threadIdx.x & 15;      // lane within half-warp

    const __half* hin = (k == 1) ? g_xh : (g_hh + (size_t)(k - 2) * SZ);
    const uint4* __restrict__ hv = (const uint4*)hin;
    uint4* __restrict__ ho = (uint4*)(g_hh + (size_t)(k - 1) * SZ);
    const float sc = exp2f(-(float)g_d[k]);   // exact power of 2

    for (int node = hw0; node < N_NODES; node += N_HW) {
        const int beg = g_rowptr[node];
        const int end = g_rowptr[node + 1];

        float a[8] = {0.f, 0.f, 0.f, 0.f, 0.f, 0.f, 0.f, 0.f};

        for (int e0 = beg; e0 < end; e0 += 8) {
            const int rem = end - e0;
            int  s[8];
            uint4 u[8];
#pragma unroll
            for (int j = 0; j < 8; j++)
                s[j] = (j < rem) ? __ldg(&g_col[e0 + j]) : 0;
#pragma unroll
            for (int j = 0; j < 8; j++)
                u[j] = (j < rem) ? __ldg(&hv[s[j] * 16 + sub])
                                 : make_uint4(0u, 0u, 0u, 0u);
#pragma unroll
            for (int j = 0; j < 8; j++) {
                float2 p;
                p = __half22float2(*(__half2*)&u[j].x); a[0] += p.x; a[1] += p.y;
                p = __half22float2(*(__half2*)&u[j].y); a[2] += p.x; a[3] += p.y;
                p = __half22float2(*(__half2*)&u[j].z); a[4] += p.x; a[5] += p.y;
                p = __half22float2(*(__half2*)&u[j].w); a[6] += p.x; a[7] += p.y;
            }
        }

#pragma unroll
        for (int i = 0; i < 8; i++) a[i] *= sc;

        __half2 h0 = __floats2half2_rn(a[0], a[1]);
        __half2 h1 = __floats2half2_rn(a[2], a[3]);
        __half2 h2 = __floats2half2_rn(a[4], a[5]);
        __half2 h3 = __floats2half2_rn(a[6], a[7]);
        uint4 st;
        st.x = *(unsigned*)&h0;
        st.y = *(unsigned*)&h1;
        st.z = *(unsigned*)&h2;
        st.w = *(unsigned*)&h3;
        ho[node * 16 + sub] = st;
    }
}

// ---------------------------------------------------------------------------
// final combine: out = w0*x + sum_k w_k * 2^{E_k} * stored_k,  E_k = sum d_j
// ---------------------------------------------------------------------------
__global__ void __launch_bounds__(256)
combine_kernel(const float* __restrict__ x, float* __restrict__ out) {
    int i = blockIdx.x * blockDim.x + threadIdx.x;   // uint4 index (8 halves)
    if (i >= SZ / 8) return;

    float f[K_HOPS + 1];
    {
        int E = 0;
        for (int k = 1; k <= K_HOPS; k++) {
            E += g_d[k];
            f[k] = g_w[k] * exp2f((float)E);
        }
        f[0] = g_w[0];
    }

    float4 xa = ((const float4*)x)[i * 2];
    float4 xb = ((const float4*)x)[i * 2 + 1];
    float4 ra, rb;
    ra.x = f[0] * xa.x; ra.y = f[0] * xa.y; ra.z = f[0] * xa.z; ra.w = f[0] * xa.w;
    rb.x = f[0] * xb.x; rb.y = f[0] * xb.y; rb.z = f[0] * xb.z; rb.w = f[0] * xb.w;

#pragma unroll
    for (int k = 1; k <= K_HOPS; k++) {
        uint4 u = __ldg(&((const uint4*)(g_hh + (size_t)(k - 1) * SZ))[i]);
        float2 p0 = __half22float2(*(__half2*)&u.x);
        float2 p1 = __half22float2(*(__half2*)&u.y);
        float2 p2 = __half22float2(*(__half2*)&u.z);
        float2 p3 = __half22float2(*(__half2*)&u.w);
        ra.x += f[k] * p0.x; ra.y += f[k] * p0.y;
        ra.z += f[k] * p1.x; ra.w += f[k] * p1.y;
        rb.x += f[k] * p2.x; rb.y += f[k] * p2.y;
        rb.z += f[k] * p3.x; rb.w += f[k] * p3.y;
    }
    ((float4*)out)[i * 2]     = ra;
    ((float4*)out)[i * 2 + 1] = rb;
}

// ---------------------------------------------------------------------------
// launch
// ---------------------------------------------------------------------------
extern "C" void kernel_launch(void* const* d_in, const int* in_sizes, int n_in,
                              void* d_out, int out_size) {
    const float* x   = nullptr;
    const float* att = nullptr;
    const void*  ei  = nullptr;
    for (int i = 0; i < n_in; i++) {
        if (in_sizes[i] == SZ)               x   = (const float*)d_in[i];
        else if (in_sizes[i] == K_HOPS + 1)  att = (const float*)d_in[i];
        else if (in_sizes[i] == 2 * N_EDGES) ei  = d_in[i];
    }
    float* out = (float*)d_out;

    prep_kernel<<<1, 32>>>(ei, att);
    quantize_x_kernel<<<296, 256>>>(x);   // also zeros g_deg

    hist_kernel<<<((N_EDGES + 3) / 4 + 255) / 256, 256>>>(ei);
    scan_reduce_kernel<<<N_TILES, SCAN_TILE>>>();
    scan_tiles_kernel<<<1, 128>>>();      // also computes scale plan
    scan_final_kernel<<<N_TILES, SCAN_TILE>>>();
    scatter_kernel<<<((N_EDGES + 3) / 4 + 255) / 256, 256>>>(ei);

    for (int k = 1; k <= K_HOPS; k++) {
        prop_kernel<<<PROP_BLOCKS, PROP_THREADS>>>(k);
    }

    combine_kernel<<<(SZ / 8 + 255) / 256, 256>>>(x, out);
}

// round 15
// speedup vs baseline: 1.1884x; 1.1884x over previous
#include <cuda_runtime.h>
#include <cuda_fp16.h>

#define N_NODES 50000
#define N_EDGES 625000
#define D_FEAT  128
#define K_HOPS  10
#define SZ      (N_NODES * D_FEAT)

#define SCAN_TILE 512
#define N_TILES   ((N_NODES + SCAN_TILE - 1) / SCAN_TILE)   // 98

// ---------------------------------------------------------------------------
// Scratch (device globals — no allocation allowed anywhere)
// ---------------------------------------------------------------------------
__device__ __half g_hh[(size_t)K_HOPS * SZ];  // h_k (scaled) at slot k-1
__device__ __half g_xh[SZ];                   // fp16(x), 12.8 MB
__device__ int    g_deg[N_NODES];
__device__ int    g_rowptr[N_NODES + 1];
__device__ int    g_cursor[N_NODES];
__device__ int    g_col[N_EDGES];
__device__ float  g_w[K_HOPS + 1];
__device__ int    g_is64;
__device__ int    g_tilesum[N_TILES];
__device__ int    g_tileoff[N_TILES];
__device__ float  g_S0;              // max|x|
__device__ int    g_d[K_HOPS + 1];   // per-hop scale exponent d_k (precomputed)
__device__ int    g_maxdeg;

__device__ __forceinline__ void atomicMaxF(float* addr, float v) {
    atomicMax((int*)addr, __float_as_int(v));   // valid: non-negative floats
}

// ---------------------------------------------------------------------------
// 0) dtype detect + softmax(att) + zero per-launch scalars
// ---------------------------------------------------------------------------
__global__ void prep_kernel(const void* ei, const float* __restrict__ att) {
    if (threadIdx.x == 0 && blockIdx.x == 0) {
        const long long* p = (const long long*)ei;
        int is64 = 1;
        for (int i = 0; i < 64; i++) {
            long long v = p[i];
            if (v < 0 || v >= (long long)N_NODES) { is64 = 0; break; }
        }
        g_is64 = is64;

        float m = -1e30f;
        for (int i = 0; i <= K_HOPS; i++) m = fmaxf(m, att[i]);
        float e[K_HOPS + 1];
        float s = 0.f;
        for (int i = 0; i <= K_HOPS; i++) { e[i] = __expf(att[i] - m); s += e[i]; }
        float inv = 1.f / s;
        for (int i = 0; i <= K_HOPS; i++) g_w[i] = e[i] * inv;

        for (int i = 0; i <= K_HOPS; i++) g_d[i] = 0;
        g_S0 = 0.f;
        g_maxdeg = 0;
    }
}

// fused: x -> fp16 g_xh, max|x| -> g_S0, AND zero g_deg
__global__ void __launch_bounds__(256)
quantize_x_kernel(const float* __restrict__ x) {
    const int stride = gridDim.x * blockDim.x;
    int t = blockIdx.x * blockDim.x + threadIdx.x;

    for (int i = t; i < N_NODES; i += stride) g_deg[i] = 0;

    float m = 0.f;
    for (int i = t; i < SZ / 4; i += stride) {
        float4 v = __ldg(&((const float4*)x)[i]);
        m = fmaxf(m, fmaxf(fmaxf(fabsf(v.x), fabsf(v.y)),
                           fmaxf(fabsf(v.z), fabsf(v.w))));
        __half2 h01 = __floats2half2_rn(v.x, v.y);
        __half2 h23 = __floats2half2_rn(v.z, v.w);
        uint2 st;
        st.x = *(unsigned*)&h01;
        st.y = *(unsigned*)&h23;
        ((uint2*)g_xh)[i] = st;
    }
    for (int off = 16; off > 0; off >>= 1)
        m = fmaxf(m, __shfl_down_sync(0xFFFFFFFFu, m, off));
    if ((threadIdx.x & 31) == 0) atomicMaxF(&g_S0, m);
}

// ---------------------------------------------------------------------------
// CSR build
// ---------------------------------------------------------------------------
__global__ void hist_kernel(const void* __restrict__ ei) {
    int t = blockIdx.x * blockDim.x + threadIdx.x;
    int e = t * 4;
    if (e >= N_EDGES) return;
    int d0, d1, d2, d3;
    if (g_is64) {
        const longlong2* p = (const longlong2*)((const long long*)ei + N_EDGES);
        longlong2 a = p[t * 2];
        longlong2 b = p[t * 2 + 1];
        d0 = (int)a.x; d1 = (int)a.y; d2 = (int)b.x; d3 = (int)b.y;
    } else {
        int4 a = ((const int4*)((const int*)ei + N_EDGES))[t];
        d0 = a.x; d1 = a.y; d2 = a.z; d3 = a.w;
    }
    atomicAdd(&g_deg[d0], 1);
    if (e + 1 < N_EDGES) atomicAdd(&g_deg[d1], 1);
    if (e + 2 < N_EDGES) atomicAdd(&g_deg[d2], 1);
    if (e + 3 < N_EDGES) atomicAdd(&g_deg[d3], 1);
}

__global__ void __launch_bounds__(SCAN_TILE)
scan_reduce_kernel() {
    __shared__ int wsum[SCAN_TILE / 32];
    int i = blockIdx.x * SCAN_TILE + threadIdx.x;
    int v = (i < N_NODES) ? g_deg[i] : 0;
    int mx = v;
    for (int off = 16; off > 0; off >>= 1) {
        v  += __shfl_down_sync(0xFFFFFFFFu, v,  off);
        mx  = max(mx, __shfl_down_sync(0xFFFFFFFFu, mx, off));
    }
    int wid = threadIdx.x >> 5;
    if ((threadIdx.x & 31) == 0) { wsum[wid] = v; atomicMax(&g_maxdeg, mx); }
    __syncthreads();
    if (wid == 0) {
        int lane = threadIdx.x & 31;
        int s = (lane < SCAN_TILE / 32) ? wsum[lane] : 0;
        for (int off = 16; off > 0; off >>= 1)
            s += __shfl_down_sync(0xFFFFFFFFu, s, off);
        if (lane == 0) g_tilesum[blockIdx.x] = s;
    }
}

// tile-sum exclusive scan + fused deterministic scale plan
__global__ void scan_tiles_kernel() {
    __shared__ int wtot[4];
    int tid  = threadIdx.x;
    int lane = tid & 31;
    int wid  = tid >> 5;
    int v = (tid < N_TILES) ? g_tilesum[tid] : 0;
    int incl = v;
    for (int off = 1; off < 32; off <<= 1) {
        int u = __shfl_up_sync(0xFFFFFFFFu, incl, off);
        if (lane >= off) incl += u;
    }
    if (lane == 31) wtot[wid] = incl;
    __syncthreads();
    int base = 0;
    for (int w = 0; w < wid; w++) base += wtot[w];
    int excl = base + incl - v;
    if (tid < N_TILES) g_tileoff[tid] = excl;
    if (tid == N_TILES - 1) g_rowptr[N_NODES] = excl + v;

    // scale plan: bound chain S_k <= S_{k-1}*maxdeg*2^{-d_k} (exact pow2,
    // fp16 precision is scale-invariant; guarantees no overflow).
    if (tid == 0) {
        float S  = g_S0;
        float md = (float)g_maxdeg;
        for (int k = 1; k <= K_HOPS; k++) {
            float bound = S * md;
            int d = 0;
            if (bound > 32768.f) d = (int)ceilf(log2f(bound * (1.f / 32768.f)));
            g_d[k] = d;
            S = bound * exp2f(-(float)d);
        }
    }
}

__global__ void __launch_bounds__(SCAN_TILE)
scan_final_kernel() {
    __shared__ int wtot[SCAN_TILE / 32];
    int i    = blockIdx.x * SCAN_TILE + threadIdx.x;
    int lane = threadIdx.x & 31;
    int wid  = threadIdx.x >> 5;

    int v = (i < N_NODES) ? g_deg[i] : 0;
    int incl = v;
    for (int off = 1; off < 32; off <<= 1) {
        int u = __shfl_up_sync(0xFFFFFFFFu, incl, off);
        if (lane >= off) incl += u;
    }
    if (lane == 31) wtot[wid] = incl;
    __syncthreads();
    if (wid == 0) {
        int s = (lane < SCAN_TILE / 32) ? wtot[lane] : 0;
        int si = s;
        for (int off = 1; off < 32; off <<= 1) {
            int u = __shfl_up_sync(0xFFFFFFFFu, si, off);
            if (lane >= off) si += u;
        }
        if (lane < SCAN_TILE / 32) wtot[lane] = si - s;
    }
    __syncthreads();

    if (i < N_NODES) {
        int excl = g_tileoff[blockIdx.x] + wtot[wid] + incl - v;
        g_rowptr[i] = excl;
        g_cursor[i] = excl;
    }
}

__global__ void scatter_kernel(const void* __restrict__ ei) {
    int t = blockIdx.x * blockDim.x + threadIdx.x;
    int e = t * 4;
    if (e >= N_EDGES) return;
    int s0, s1, s2, s3, d0, d1, d2, d3;
    if (g_is64) {
        const long long* p = (const long long*)ei;
        longlong2 sa = ((const longlong2*)p)[t * 2];
        longlong2 sb = ((const longlong2*)p)[t * 2 + 1];
        longlong2 da = ((const longlong2*)(p + N_EDGES))[t * 2];
        longlong2 db = ((const longlong2*)(p + N_EDGES))[t * 2 + 1];
        s0 = (int)sa.x; s1 = (int)sa.y; s2 = (int)sb.x; s3 = (int)sb.y;
        d0 = (int)da.x; d1 = (int)da.y; d2 = (int)db.x; d3 = (int)db.y;
    } else {
        const int* p = (const int*)ei;
        int4 sa = ((const int4*)p)[t];
        int4 da = ((const int4*)(p + N_EDGES))[t];
        s0 = sa.x; s1 = sa.y; s2 = sa.z; s3 = sa.w;
        d0 = da.x; d1 = da.y; d2 = da.z; d3 = da.w;
    }
    { int q = atomicAdd(&g_cursor[d0], 1); g_col[q] = s0; }
    if (e + 1 < N_EDGES) { int q = atomicAdd(&g_cursor[d1], 1); g_col[q] = s1; }
    if (e + 2 < N_EDGES) { int q = atomicAdd(&g_cursor[d2], 1); g_col[q] = s2; }
    if (e + 3 < N_EDGES) { int q = atomicAdd(&g_cursor[d3], 1); g_col[q] = s3; }
}

// ---------------------------------------------------------------------------
// propagation hop k: HALF-WARP per node (one node per half-warp — max TLP,
// the R14 grid-stride experiment showed this is required), fp16, uint4
// loads, chunk-8 MLP. Hops 1..9 store stored_k = (A*stored_{k-1})*2^{-d_k}.
// Hop 10 (final=true) fuses the combine epilogue:
//   out = w0*x + sum_{j<10} w_j*2^{E_j}*stored_j + w_10*2^{E_10}*acc
// saving the h_10 store + reload and the separate combine kernel.
// ---------------------------------------------------------------------------
__global__ void __launch_bounds__(512)
prop_kernel(int k, const float* __restrict__ x, float* __restrict__ out) {
    const int tid  = blockIdx.x * blockDim.x + threadIdx.x;
    const int node = tid >> 4;              // half-warp per node
    const int sub  = threadIdx.x & 15;      // lane within half-warp
    if (node >= N_NODES) return;

    const __half* hin = (k == 1) ? g_xh : (g_hh + (size_t)(k - 2) * SZ);
    const uint4* __restrict__ hv = (const uint4*)hin;
    const int beg = g_rowptr[node];
    const int end = g_rowptr[node + 1];

    float a[8] = {0.f, 0.f, 0.f, 0.f, 0.f, 0.f, 0.f, 0.f};

    for (int e0 = beg; e0 < end; e0 += 8) {
        const int rem = end - e0;
        int  s[8];
        uint4 u[8];
#pragma unroll
        for (int j = 0; j < 8; j++)
            s[j] = (j < rem) ? __ldg(&g_col[e0 + j]) : 0;
#pragma unroll
        for (int j = 0; j < 8; j++)
            u[j] = (j < rem) ? __ldg(&hv[s[j] * 16 + sub])
                             : make_uint4(0u, 0u, 0u, 0u);
#pragma unroll
        for (int j = 0; j < 8; j++) {
            float2 p;
            p = __half22float2(*(__half2*)&u[j].x); a[0] += p.x; a[1] += p.y;
            p = __half22float2(*(__half2*)&u[j].y); a[2] += p.x; a[3] += p.y;
            p = __half22float2(*(__half2*)&u[j].z); a[4] += p.x; a[5] += p.y;
            p = __half22float2(*(__half2*)&u[j].w); a[6] += p.x; a[7] += p.y;
        }
    }

    const float sc = exp2f(-(float)g_d[k]);   // exact power of 2
#pragma unroll
    for (int i = 0; i < 8; i++) a[i] *= sc;

    if (k < K_HOPS) {
        __half2 h0 = __floats2half2_rn(a[0], a[1]);
        __half2 h1 = __floats2half2_rn(a[2], a[3]);
        __half2 h2 = __floats2half2_rn(a[4], a[5]);
        __half2 h3 = __floats2half2_rn(a[6], a[7]);
        uint4 st;
        st.x = *(unsigned*)&h0;
        st.y = *(unsigned*)&h1;
        st.z = *(unsigned*)&h2;
        st.w = *(unsigned*)&h3;
        ((uint4*)(g_hh + (size_t)(k - 1) * SZ))[node * 16 + sub] = st;
        return;
    }

    // ---- fused combine epilogue (k == K_HOPS) ----
    float f[K_HOPS + 1];
    {
        int E = 0;
#pragma unroll
        for (int j = 1; j <= K_HOPS; j++) {
            E += g_d[j];
            f[j] = g_w[j] * exp2f((float)E);
        }
        f[0] = g_w[0];
    }

    // out rows: this node's 8 features [8*sub, 8*sub+8)
    const int fbase = node * 32 + sub * 2;       // float4 index into x / out
    float4 xa = __ldg(&((const float4*)x)[fbase]);
    float4 xb = __ldg(&((const float4*)x)[fbase + 1]);
    float r[8];
    r[0] = f[0] * xa.x; r[1] = f[0] * xa.y; r[2] = f[0] * xa.z; r[3] = f[0] * xa.w;
    r[4] = f[0] * xb.x; r[5] = f[0] * xb.y; r[6] = f[0] * xb.z; r[7] = f[0] * xb.w;

    // stored_10 term in fp32 (skips one fp16 rounding)
#pragma unroll
    for (int i = 0; i < 8; i++) r[i] += f[K_HOPS] * a[i];

#pragma unroll
    for (int j = 1; j < K_HOPS; j++) {
        uint4 u = __ldg(&((const uint4*)(g_hh + (size_t)(j - 1) * SZ))[node * 16 + sub]);
        float2 p0 = __half22float2(*(__half2*)&u.x);
        float2 p1 = __half22float2(*(__half2*)&u.y);
        float2 p2 = __half22float2(*(__half2*)&u.z);
        float2 p3 = __half22float2(*(__half2*)&u.w);
        r[0] += f[j] * p0.x; r[1] += f[j] * p0.y;
        r[2] += f[j] * p1.x; r[3] += f[j] * p1.y;
        r[4] += f[j] * p2.x; r[5] += f[j] * p2.y;
        r[6] += f[j] * p3.x; r[7] += f[j] * p3.y;
    }

    float4 oa, ob;
    oa.x = r[0]; oa.y = r[1]; oa.z = r[2]; oa.w = r[3];
    ob.x = r[4]; ob.y = r[5]; ob.z = r[6]; ob.w = r[7];
    ((float4*)out)[fbase]     = oa;
    ((float4*)out)[fbase + 1] = ob;
}

// ---------------------------------------------------------------------------
// launch
// ---------------------------------------------------------------------------
extern "C" void kernel_launch(void* const* d_in, const int* in_sizes, int n_in,
                              void* d_out, int out_size) {
    const float* x   = nullptr;
    const float* att = nullptr;
    const void*  ei  = nullptr;
    for (int i = 0; i < n_in; i++) {
        if (in_sizes[i] == SZ)               x   = (const float*)d_in[i];
        else if (in_sizes[i] == K_HOPS + 1)  att = (const float*)d_in[i];
        else if (in_sizes[i] == 2 * N_EDGES) ei  = d_in[i];
    }
    float* out = (float*)d_out;

    prep_kernel<<<1, 32>>>(ei, att);
    quantize_x_kernel<<<296, 256>>>(x);   // also zeros g_deg

    hist_kernel<<<((N_EDGES + 3) / 4 + 255) / 256, 256>>>(ei);
    scan_reduce_kernel<<<N_TILES, SCAN_TILE>>>();
    scan_tiles_kernel<<<1, 128>>>();      // also computes scale plan
    scan_final_kernel<<<N_TILES, SCAN_TILE>>>();
    scatter_kernel<<<((N_EDGES + 3) / 4 + 255) / 256, 256>>>(ei);

    const int prop_blocks = (N_NODES * 16 + 511) / 512;   // half-warp per node
    for (int k = 1; k <= K_HOPS; k++) {
        prop_kernel<<<prop_blocks, 512>>>(k, x, out);
    }
}